// round 8
// baseline (speedup 1.0000x reference)
#include <cuda_runtime.h>
#include <cstdint>

#define BS 2048
#define SEQL 50
#define ATTD 64
#define HIDD 128
#define NB 16
#define NTILE (BS / NB) /* 128 */

typedef unsigned long long ull;

// ---------------- device scratch (no runtime allocation allowed) ----------------
__device__ float g_WqF[64 * 19];
__device__ float g_bq2[64];
__device__ float g_WvF[64 * 19];
__device__ float g_bv2[64];
__device__ float g_WihT[64 * 512];   // [k][g]
__device__ float g_WhhT[128 * 512];  // [k][g]
__device__ float g_bC[512];
__device__ float g_WoutT[128 * 64];  // [k][o]
__device__ float g_ctx[SEQL * BS * ATTD]; // layout [s][tile][c][16]  (~25 MB)

// ---------------- packed fp32x2 helpers (Blackwell FFMA2) ----------------
__device__ __forceinline__ ull pack2f(float w) {
    ull r; asm("mov.b64 %0, {%1, %1};" : "=l"(r) : "f"(w)); return r;
}
__device__ __forceinline__ void fma2(ull& d, ull a, ull b) {
    asm("fma.rn.f32x2 %0, %1, %2, %0;" : "+l"(d) : "l"(a), "l"(b));
}
__device__ __forceinline__ float fast_sigmoid(float x) {
    return __fdividef(1.f, 1.f + __expf(-x));
}
__device__ __forceinline__ float fast_tanh(float x) {
    return __fdividef(2.f, 1.f + __expf(-2.f * x)) - 1.f;
}

// ---------------- prep: fold W_fus into Wq/Wv, transpose LSTM/out weights ----------------
__global__ __launch_bounds__(256) void prep_kernel(
                            const float* __restrict__ W_fus, const float* __restrict__ b_fus,
                            const float* __restrict__ Wq, const float* __restrict__ bq,
                            const float* __restrict__ Wv, const float* __restrict__ bv,
                            const float* __restrict__ W_ih, const float* __restrict__ W_hh,
                            const float* __restrict__ b_ih, const float* __restrict__ b_hh,
                            const float* __restrict__ W_out) {
    int t = threadIdx.x;
    int nt = blockDim.x;
    // fused weights: (Wq @ W_fus) and (Wv @ W_fus): 64x19 each
    for (int i = t; i < 2 * 64 * 19; i += nt) {
        int sel = i / (64 * 19);
        int rem = i % (64 * 19);
        int row = rem / 19, j = rem % 19;
        const float* Wm = sel ? Wv : Wq;
        float acc = 0.f;
        for (int m = 0; m < 64; m++) acc += Wm[row * 64 + m] * W_fus[m * 19 + j];
        (sel ? g_WvF : g_WqF)[row * 19 + j] = acc;
    }
    // fused biases: Wq@b_fus + bq, Wv@b_fus + bv
    for (int i = t; i < 2 * 64; i += nt) {
        int sel = i >> 6; int row = i & 63;
        const float* Wm = sel ? Wv : Wq;
        float acc = sel ? bv[row] : bq[row];
        for (int m = 0; m < 64; m++) acc += Wm[row * 64 + m] * b_fus[m];
        (sel ? g_bv2 : g_bq2)[row] = acc;
    }
    // transposes
    for (int i = t; i < 512 * 64; i += nt)  g_WihT[(i & 63) * 512 + (i >> 6)] = W_ih[i];
    for (int i = t; i < 512 * 128; i += nt) g_WhhT[(i & 127) * 512 + (i >> 7)] = W_hh[i];
    for (int i = t; i < 512; i += nt)       g_bC[i] = b_ih[i] + b_hh[i];
    for (int i = t; i < 64 * 128; i += nt)  g_WoutT[(i & 127) * 64 + (i >> 7)] = W_out[i];
}

// ---------------- kernel A: attention -> ctx (pre-transposed [s][tile][c][16]) ----------------
__global__ __launch_bounds__(1024) void ctx_kernel(
    const float* __restrict__ seqs, const float* __restrict__ ets,
    const int* __restrict__ masks, const float* __restrict__ Wk,
    const float* __restrict__ bk) {
    __shared__ float sWq[64 * 19], sWv[64 * 19], sWk[64 * 6];
    __shared__ float sbq[64], sbv[64], sbk[64];
    __shared__ float sSeq[16 * 54];
    __shared__ float sEt[16 * 36];
    __shared__ int   sMask[16 * 9];
    __shared__ float sCtx[64 * 17];

    int tid = threadIdx.x;
    int s = blockIdx.x / NTILE;
    int tile = blockIdx.x % NTILE;

    for (int i = tid; i < 64 * 19; i += 1024) { sWq[i] = g_WqF[i]; sWv[i] = g_WvF[i]; }
    for (int i = tid; i < 64 * 6; i += 1024) sWk[i] = Wk[i];
    if (tid < 64) { sbq[tid] = g_bq2[tid]; sbv[tid] = g_bv2[tid]; sbk[tid] = bk[tid]; }

    int b_in = tid >> 6, c = tid & 63;
    int b = tile * NB + b_in;
    size_t base = (size_t)b * SEQL + s;
    if (c < 54) sSeq[b_in * 54 + c] = seqs[base * 54 + c];
    if (c < 36) sEt[b_in * 36 + c]  = ets[base * 36 + c];
    if (c < 9)  sMask[b_in * 9 + c] = masks[base * 9 + c];
    __syncthreads();

    const float* wq = sWq + c * 19;
    const float* wv = sWv + c * 19;
    // key from self node (1,1) -> n=4
    float key = sbk[c];
    #pragma unroll
    for (int j = 0; j < 6; j++) key += sSeq[b_in * 54 + 24 + j] * sWk[c * 6 + j];

    float v[9], p[9];
    #pragma unroll
    for (int n = 0; n < 9; n++) {
        float q  = sbq[c] + wq[10 + n];   // eye-part folds into per-node bias
        float vv = sbv[c] + wv[10 + n];
        #pragma unroll
        for (int j = 0; j < 6; j++) {
            float x = sSeq[b_in * 54 + n * 6 + j];
            q += x * wq[j]; vv += x * wv[j];
        }
        #pragma unroll
        for (int j = 0; j < 4; j++) {
            float x = sEt[b_in * 36 + n * 4 + j];
            q += x * wq[6 + j]; vv += x * wv[6 + j];
        }
        v[n] = vv;
        p[n] = key * q;
    }
    // reduce over 16-lane head groups
    #pragma unroll
    for (int n = 0; n < 9; n++) {
        float t = p[n];
        t += __shfl_xor_sync(0xffffffffu, t, 8);
        t += __shfl_xor_sync(0xffffffffu, t, 4);
        t += __shfl_xor_sync(0xffffffffu, t, 2);
        t += __shfl_xor_sync(0xffffffffu, t, 1);
        p[n] = t;
    }
    // mask + stable softmax over n
    float mx = -3.4e38f;
    #pragma unroll
    for (int n = 0; n < 9; n++) {
        float a = (sMask[b_in * 9 + n] == 0) ? -1e10f : p[n] * 0.25f;
        p[n] = a;
        mx = fmaxf(mx, a);
    }
    float sum = 0.f;
    #pragma unroll
    for (int n = 0; n < 9; n++) { float e = __expf(p[n] - mx); p[n] = e; sum += e; }
    float inv = __fdividef(1.f, sum);
    float ctx = 0.f;
    #pragma unroll
    for (int n = 0; n < 9; n++) ctx += p[n] * v[n];
    ctx *= inv;

    sCtx[c * 17 + b_in] = ctx;
    __syncthreads();
    // write pre-transposed tile: [c][b_in] contiguous, fully coalesced
    size_t obase = (size_t)(s * NTILE + tile) * 1024;
    g_ctx[obase + tid] = sCtx[(tid >> 4) * 17 + (tid & 15)];
}

// ---------------- kernel B: LSTM (each block owns 16 batch rows for all 50 steps) ----------------
__global__ __launch_bounds__(512) void lstm_kernel(const float* __restrict__ b_out,
                                                   float* __restrict__ out) {
    __shared__ __align__(16) float xs[64 * 16];    // [k][b]
    __shared__ __align__(16) float hsb[128 * 20];  // [k][b], pad 20 keeps 16B alignment
    __shared__ float sAct[16 * 512];               // [b][g]
    int tid = threadIdx.x;
    int tile = blockIdx.x;
    int g = tid;
    int region = g >> 7;  // 0=i 1=f 2=g 3=o

    for (int i = tid; i < 128 * 20; i += 512) hsb[i] = 0.f;
    float cst[4] = {0.f, 0.f, 0.f, 0.f};
    float bias = g_bC[g];
    const float* Wx = g_WihT + g;
    const float* Wh = g_WhhT + g;
    const float4* ctxsrc = (const float4*)g_ctx;

    for (int s = 0; s < SEQL; s++) {
        __syncthreads();
        if (tid < 256) ((float4*)xs)[tid] = ctxsrc[(size_t)(s * NTILE + tile) * 256 + tid];
        __syncthreads();

        ull acc[8];
        ull bi = pack2f(bias);
        #pragma unroll
        for (int pp = 0; pp < 8; pp++) acc[pp] = bi;

        #pragma unroll 8
        for (int k = 0; k < 64; k++) {
            ull w2 = pack2f(Wx[k * 512]);           // coalesced, L2-resident
            const ulonglong2* xr = (const ulonglong2*)(xs + k * 16);
            ulonglong2 a0 = xr[0], a1 = xr[1], a2 = xr[2], a3 = xr[3];
            fma2(acc[0], w2, a0.x); fma2(acc[1], w2, a0.y);
            fma2(acc[2], w2, a1.x); fma2(acc[3], w2, a1.y);
            fma2(acc[4], w2, a2.x); fma2(acc[5], w2, a2.y);
            fma2(acc[6], w2, a3.x); fma2(acc[7], w2, a3.y);
        }
        #pragma unroll 8
        for (int k = 0; k < 128; k++) {
            ull w2 = pack2f(Wh[k * 512]);
            const ulonglong2* hr = (const ulonglong2*)(hsb + k * 20);
            ulonglong2 a0 = hr[0], a1 = hr[1], a2 = hr[2], a3 = hr[3];
            fma2(acc[0], w2, a0.x); fma2(acc[1], w2, a0.y);
            fma2(acc[2], w2, a1.x); fma2(acc[3], w2, a1.y);
            fma2(acc[4], w2, a2.x); fma2(acc[5], w2, a2.y);
            fma2(acc[6], w2, a3.x); fma2(acc[7], w2, a3.y);
        }
        #pragma unroll
        for (int pp = 0; pp < 8; pp++) {
            float lo = __uint_as_float((unsigned)acc[pp]);
            float hi = __uint_as_float((unsigned)(acc[pp] >> 32));
            if (region == 2) { lo = fast_tanh(lo); hi = fast_tanh(hi); }
            else             { lo = fast_sigmoid(lo); hi = fast_sigmoid(hi); }
            sAct[(2 * pp) * 512 + g] = lo;
            sAct[(2 * pp + 1) * 512 + g] = hi;
        }
        __syncthreads();
        // c/h update: thread r-slot owns fixed (b,j) across all steps -> c stays in regs
        #pragma unroll
        for (int r = 0; r < 4; r++) {
            int idx = tid + 512 * r;
            int j = idx & 127, bb = idx >> 7;
            float iv = sAct[bb * 512 + j];
            float fv = sAct[bb * 512 + 128 + j];
            float gv = sAct[bb * 512 + 256 + j];
            float ov = sAct[bb * 512 + 384 + j];
            float cc = fv * cst[r] + iv * gv;
            cst[r] = cc;
            hsb[j * 20 + bb] = ov * fast_tanh(cc);
        }
    }
    __syncthreads();
    // output projection: out[b][o] = b_out[o] + sum_k h[b][k] * W_out[o][k]
    #pragma unroll
    for (int r = 0; r < 2; r++) {
        int idx = tid + 512 * r;
        int o = idx & 63, bb = idx >> 6;
        float a = b_out[o];
        #pragma unroll 16
        for (int k = 0; k < 128; k++) a += hsb[k * 20 + bb] * g_WoutT[k * 64 + o];
        out[(size_t)(tile * NB + bb) * 64 + o] = a;
    }
}

// ---------------- launch ----------------
extern "C" void kernel_launch(void* const* d_in, const int* in_sizes, int n_in,
                              void* d_out, int out_size) {
    const float* seqs  = (const float*)d_in[0];
    const float* ets   = (const float*)d_in[1];
    const int*   masks = (const int*)d_in[2];
    const float* W_fus = (const float*)d_in[3];
    const float* b_fus = (const float*)d_in[4];
    const float* Wk    = (const float*)d_in[5];
    const float* bk    = (const float*)d_in[6];
    const float* Wq    = (const float*)d_in[7];
    const float* bq    = (const float*)d_in[8];
    const float* Wv    = (const float*)d_in[9];
    const float* bv    = (const float*)d_in[10];
    const float* W_ih  = (const float*)d_in[11];
    const float* W_hh  = (const float*)d_in[12];
    const float* b_ih  = (const float*)d_in[13];
    const float* b_hh  = (const float*)d_in[14];
    const float* W_out = (const float*)d_in[15];
    const float* b_out = (const float*)d_in[16];
    float* out = (float*)d_out;

    prep_kernel<<<1, 256>>>(W_fus, b_fus, Wq, bq, Wv, bv, W_ih, W_hh, b_ih, b_hh, W_out);
    ctx_kernel<<<SEQL * NTILE, 1024>>>(seqs, ets, masks, Wk, bk);
    lstm_kernel<<<NTILE, 512>>>(b_out, out);
}

// round 11
// speedup vs baseline: 1.1959x; 1.1959x over previous
#include <cuda_runtime.h>
#include <cstdint>

#define BS 2048
#define SEQL 50
#define ATTD 64
#define HIDD 128
#define NB 16
#define NTILE (BS / NB) /* 128 */

typedef unsigned long long ull;

// ---------------- device scratch (no runtime allocation allowed) ----------------
__device__ float g_WqF[64 * 19];
__device__ float g_bq2[64];
__device__ float g_WvF[64 * 19];
__device__ float g_bv2[64];
__device__ float g_WihT[64 * 512];   // [k][g]
__device__ float g_WhhT[128 * 512];  // [k][g]
__device__ float g_bC[512];
__device__ float g_WoutT[128 * 64];  // [k][o]
__device__ float g_ctx[SEQL * BS * ATTD]; // layout [s][tile][c][16]  (~25 MB)

// ---------------- packed fp32x2 helpers (Blackwell FFMA2) ----------------
__device__ __forceinline__ ull pack2f(float w) {
    ull r; asm("mov.b64 %0, {%1, %1};" : "=l"(r) : "f"(w)); return r;
}
__device__ __forceinline__ void fma2(ull& d, ull a, ull b) {
    asm("fma.rn.f32x2 %0, %1, %2, %0;" : "+l"(d) : "l"(a), "l"(b));
}
__device__ __forceinline__ float fast_sigmoid(float x) {
    return __fdividef(1.f, 1.f + __expf(-x));
}
__device__ __forceinline__ float fast_tanh(float x) {
    return __fdividef(2.f, 1.f + __expf(-2.f * x)) - 1.f;
}
__device__ __forceinline__ void cpa16(void* dst_smem, const void* src) {
    unsigned d = (unsigned)__cvta_generic_to_shared(dst_smem);
    asm volatile("cp.async.cg.shared.global [%0], [%1], 16;\n" :: "r"(d), "l"(src));
}
__device__ __forceinline__ void cpa_commit() {
    asm volatile("cp.async.commit_group;\n" ::: "memory");
}
__device__ __forceinline__ void cpa_wait_all() {
    asm volatile("cp.async.wait_group 0;\n" ::: "memory");
}

// ---------------- prep: fold W_fus into Wq/Wv, transpose LSTM/out weights ----------------
__global__ __launch_bounds__(256) void prep_kernel(
                            const float* __restrict__ W_fus, const float* __restrict__ b_fus,
                            const float* __restrict__ Wq, const float* __restrict__ bq,
                            const float* __restrict__ Wv, const float* __restrict__ bv,
                            const float* __restrict__ W_ih, const float* __restrict__ W_hh,
                            const float* __restrict__ b_ih, const float* __restrict__ b_hh,
                            const float* __restrict__ W_out) {
    int t = blockIdx.x * blockDim.x + threadIdx.x;
    int nt = gridDim.x * blockDim.x;
    // fused weights: (Wq @ W_fus) and (Wv @ W_fus): 64x19 each
    for (int i = t; i < 2 * 64 * 19; i += nt) {
        int sel = i / (64 * 19);
        int rem = i % (64 * 19);
        int row = rem / 19, j = rem % 19;
        const float* Wm = sel ? Wv : Wq;
        float acc = 0.f;
        for (int m = 0; m < 64; m++) acc += Wm[row * 64 + m] * W_fus[m * 19 + j];
        (sel ? g_WvF : g_WqF)[row * 19 + j] = acc;
    }
    // fused biases: Wq@b_fus + bq, Wv@b_fus + bv
    for (int i = t; i < 2 * 64; i += nt) {
        int sel = i >> 6; int row = i & 63;
        const float* Wm = sel ? Wv : Wq;
        float acc = sel ? bv[row] : bq[row];
        for (int m = 0; m < 64; m++) acc += Wm[row * 64 + m] * b_fus[m];
        (sel ? g_bv2 : g_bq2)[row] = acc;
    }
    // transposes
    for (int i = t; i < 512 * 64; i += nt)  g_WihT[(i & 63) * 512 + (i >> 6)] = W_ih[i];
    for (int i = t; i < 512 * 128; i += nt) g_WhhT[(i & 127) * 512 + (i >> 7)] = W_hh[i];
    for (int i = t; i < 512; i += nt)       g_bC[i] = b_ih[i] + b_hh[i];
    for (int i = t; i < 64 * 128; i += nt)  g_WoutT[(i & 127) * 64 + (i >> 7)] = W_out[i];
}

// ---------------- kernel A: attention -> ctx (pre-transposed [s][tile][c][16]) ----------------
__global__ __launch_bounds__(1024) void ctx_kernel(
    const float* __restrict__ seqs, const float* __restrict__ ets,
    const int* __restrict__ masks, const float* __restrict__ Wk,
    const float* __restrict__ bk) {
    __shared__ float sWq[64 * 19], sWv[64 * 19], sWk[64 * 6];
    __shared__ float sbq[64], sbv[64], sbk[64];
    __shared__ float sSeq[16 * 54];
    __shared__ float sEt[16 * 36];
    __shared__ int   sMask[16 * 9];
    __shared__ float sCtx[64 * 17];

    int tid = threadIdx.x;
    int s = blockIdx.x / NTILE;
    int tile = blockIdx.x % NTILE;

    for (int i = tid; i < 64 * 19; i += 1024) { sWq[i] = g_WqF[i]; sWv[i] = g_WvF[i]; }
    for (int i = tid; i < 64 * 6; i += 1024) sWk[i] = Wk[i];
    if (tid < 64) { sbq[tid] = g_bq2[tid]; sbv[tid] = g_bv2[tid]; sbk[tid] = bk[tid]; }

    int b_in = tid >> 6, c = tid & 63;
    int b = tile * NB + b_in;
    size_t base = (size_t)b * SEQL + s;
    if (c < 54) sSeq[b_in * 54 + c] = seqs[base * 54 + c];
    if (c < 36) sEt[b_in * 36 + c]  = ets[base * 36 + c];
    if (c < 9)  sMask[b_in * 9 + c] = masks[base * 9 + c];
    __syncthreads();

    const float* wq = sWq + c * 19;
    const float* wv = sWv + c * 19;
    // key from self node (1,1) -> n=4
    float key = sbk[c];
    #pragma unroll
    for (int j = 0; j < 6; j++) key += sSeq[b_in * 54 + 24 + j] * sWk[c * 6 + j];

    float v[9], p[9];
    #pragma unroll
    for (int n = 0; n < 9; n++) {
        float q  = sbq[c] + wq[10 + n];   // eye-part folds into per-node bias
        float vv = sbv[c] + wv[10 + n];
        #pragma unroll
        for (int j = 0; j < 6; j++) {
            float x = sSeq[b_in * 54 + n * 6 + j];
            q += x * wq[j]; vv += x * wv[j];
        }
        #pragma unroll
        for (int j = 0; j < 4; j++) {
            float x = sEt[b_in * 36 + n * 4 + j];
            q += x * wq[6 + j]; vv += x * wv[6 + j];
        }
        v[n] = vv;
        p[n] = key * q;
    }
    // reduce over 16-lane head groups
    #pragma unroll
    for (int n = 0; n < 9; n++) {
        float t = p[n];
        t += __shfl_xor_sync(0xffffffffu, t, 8);
        t += __shfl_xor_sync(0xffffffffu, t, 4);
        t += __shfl_xor_sync(0xffffffffu, t, 2);
        t += __shfl_xor_sync(0xffffffffu, t, 1);
        p[n] = t;
    }
    // mask + stable softmax over n
    float mx = -3.4e38f;
    #pragma unroll
    for (int n = 0; n < 9; n++) {
        float a = (sMask[b_in * 9 + n] == 0) ? -1e10f : p[n] * 0.25f;
        p[n] = a;
        mx = fmaxf(mx, a);
    }
    float sum = 0.f;
    #pragma unroll
    for (int n = 0; n < 9; n++) { float e = __expf(p[n] - mx); p[n] = e; sum += e; }
    float inv = __fdividef(1.f, sum);
    float ctx = 0.f;
    #pragma unroll
    for (int n = 0; n < 9; n++) ctx += p[n] * v[n];
    ctx *= inv;

    sCtx[c * 17 + b_in] = ctx;
    __syncthreads();
    // write pre-transposed tile: [c][b_in] contiguous, fully coalesced
    size_t obase = (size_t)(s * NTILE + tile) * 1024;
    g_ctx[obase + tid] = sCtx[(tid >> 4) * 17 + (tid & 15)];
}

// ---------------- kernel B: LSTM (each block owns 16 batch rows for all 50 steps) ----------------
__global__ __launch_bounds__(512) void lstm_kernel(const float* __restrict__ b_out,
                                                   float* __restrict__ out) {
    __shared__ __align__(16) float xsbuf[2 * 1024];  // double-buffered [k][b] tiles (4KB each)
    __shared__ __align__(16) float hsb[128 * 20];    // [k][b], pad 20 keeps 16B alignment
    __shared__ float sAct[16 * 512];                 // [b][g]
    int tid = threadIdx.x;
    int tile = blockIdx.x;
    int g = tid;
    int region = g >> 7;  // 0=i 1=f 2=g 3=o

    for (int i = tid; i < 128 * 20; i += 512) hsb[i] = 0.f;
    float cst[4] = {0.f, 0.f, 0.f, 0.f};
    float bias = g_bC[g];
    const float* Wx = g_WihT + g;
    const float* Wh = g_WhhT + g;
    const float4* ctxsrc = (const float4*)g_ctx;

    // prefetch step 0 ctx tile into buffer 0
    if (tid < 256) {
        cpa16(xsbuf + tid * 4, ctxsrc + (size_t)(0 * NTILE + tile) * 256 + tid);
        cpa_commit();
        cpa_wait_all();
    }
    int cur = 0;

    for (int s = 0; s < SEQL; s++) {
        __syncthreads();  // xs[cur] visible to all; hsb from prev step visible
        const float* xs = xsbuf + cur * 1024;
        // kick off prefetch of next step's ctx tile into the other buffer
        if (tid < 256 && s + 1 < SEQL) {
            cpa16(xsbuf + (1 - cur) * 1024 + tid * 4,
                  ctxsrc + (size_t)((s + 1) * NTILE + tile) * 256 + tid);
            cpa_commit();
        }

        ull acc[8];
        ull bi = pack2f(bias);
        #pragma unroll
        for (int pp = 0; pp < 8; pp++) acc[pp] = bi;

        // x part: 64 k, chunked by 4 with batched loads (MLP)
        #pragma unroll
        for (int kb = 0; kb < 64; kb += 4) {
            float wv[4];
            ulonglong2 rv[4][4];
            #pragma unroll
            for (int u = 0; u < 4; u++) wv[u] = Wx[(kb + u) * 512];
            #pragma unroll
            for (int u = 0; u < 4; u++) {
                const ulonglong2* xr = (const ulonglong2*)(xs + (kb + u) * 16);
                rv[u][0] = xr[0]; rv[u][1] = xr[1]; rv[u][2] = xr[2]; rv[u][3] = xr[3];
            }
            #pragma unroll
            for (int u = 0; u < 4; u++) {
                ull w2 = pack2f(wv[u]);
                fma2(acc[0], w2, rv[u][0].x); fma2(acc[1], w2, rv[u][0].y);
                fma2(acc[2], w2, rv[u][1].x); fma2(acc[3], w2, rv[u][1].y);
                fma2(acc[4], w2, rv[u][2].x); fma2(acc[5], w2, rv[u][2].y);
                fma2(acc[6], w2, rv[u][3].x); fma2(acc[7], w2, rv[u][3].y);
            }
        }
        // h part: 128 k, same chunking
        #pragma unroll
        for (int kb = 0; kb < 128; kb += 4) {
            float wv[4];
            ulonglong2 rv[4][4];
            #pragma unroll
            for (int u = 0; u < 4; u++) wv[u] = Wh[(kb + u) * 512];
            #pragma unroll
            for (int u = 0; u < 4; u++) {
                const ulonglong2* hr = (const ulonglong2*)(hsb + (kb + u) * 20);
                rv[u][0] = hr[0]; rv[u][1] = hr[1]; rv[u][2] = hr[2]; rv[u][3] = hr[3];
            }
            #pragma unroll
            for (int u = 0; u < 4; u++) {
                ull w2 = pack2f(wv[u]);
                fma2(acc[0], w2, rv[u][0].x); fma2(acc[1], w2, rv[u][0].y);
                fma2(acc[2], w2, rv[u][1].x); fma2(acc[3], w2, rv[u][1].y);
                fma2(acc[4], w2, rv[u][2].x); fma2(acc[5], w2, rv[u][2].y);
                fma2(acc[6], w2, rv[u][3].x); fma2(acc[7], w2, rv[u][3].y);
            }
        }

        #pragma unroll
        for (int pp = 0; pp < 8; pp++) {
            float lo = __uint_as_float((unsigned)acc[pp]);
            float hi = __uint_as_float((unsigned)(acc[pp] >> 32));
            if (region == 2) { lo = fast_tanh(lo); hi = fast_tanh(hi); }
            else             { lo = fast_sigmoid(lo); hi = fast_sigmoid(hi); }
            sAct[(2 * pp) * 512 + g] = lo;
            sAct[(2 * pp + 1) * 512 + g] = hi;
        }
        __syncthreads();
        // c/h update: thread r-slot owns fixed (b,j) across all steps -> c stays in regs
        #pragma unroll
        for (int r = 0; r < 4; r++) {
            int idx = tid + 512 * r;
            int j = idx & 127, bb = idx >> 7;
            float iv = sAct[bb * 512 + j];
            float fv = sAct[bb * 512 + 128 + j];
            float gv = sAct[bb * 512 + 256 + j];
            float ov = sAct[bb * 512 + 384 + j];
            float cc = fv * cst[r] + iv * gv;
            cst[r] = cc;
            hsb[j * 20 + bb] = ov * fast_tanh(cc);
        }
        // complete prefetch before the barrier that publishes it
        if (tid < 256 && s + 1 < SEQL) cpa_wait_all();
        cur ^= 1;
    }
    __syncthreads();
    // output projection: out[b][o] = b_out[o] + sum_k h[b][k] * W_out[o][k]
    #pragma unroll
    for (int r = 0; r < 2; r++) {
        int idx = tid + 512 * r;
        int o = idx & 63, bb = idx >> 6;
        float a = b_out[o];
        #pragma unroll 16
        for (int k = 0; k < 128; k++) a += hsb[k * 20 + bb] * g_WoutT[k * 64 + o];
        out[(size_t)(tile * NB + bb) * 64 + o] = a;
    }
}

// ---------------- launch ----------------
extern "C" void kernel_launch(void* const* d_in, const int* in_sizes, int n_in,
                              void* d_out, int out_size) {
    const float* seqs  = (const float*)d_in[0];
    const float* ets   = (const float*)d_in[1];
    const int*   masks = (const int*)d_in[2];
    const float* W_fus = (const float*)d_in[3];
    const float* b_fus = (const float*)d_in[4];
    const float* Wk    = (const float*)d_in[5];
    const float* bk    = (const float*)d_in[6];
    const float* Wq    = (const float*)d_in[7];
    const float* bq    = (const float*)d_in[8];
    const float* Wv    = (const float*)d_in[9];
    const float* bv    = (const float*)d_in[10];
    const float* W_ih  = (const float*)d_in[11];
    const float* W_hh  = (const float*)d_in[12];
    const float* b_ih  = (const float*)d_in[13];
    const float* b_hh  = (const float*)d_in[14];
    const float* W_out = (const float*)d_in[15];
    const float* b_out = (const float*)d_in[16];
    float* out = (float*)d_out;

    prep_kernel<<<64, 256>>>(W_fus, b_fus, Wq, bq, Wv, bv, W_ih, W_hh, b_ih, b_hh, W_out);
    ctx_kernel<<<SEQL * NTILE, 1024>>>(seqs, ets, masks, Wk, bk);
    lstm_kernel<<<NTILE, 512>>>(b_out, out);
}